// round 13
// baseline (speedup 1.0000x reference)
#include <cuda_runtime.h>
#include <math.h>

#define BJ    192
#define LSEQ  512
#define DIM   128
#define DOUT  128
#define HID   256
#define KNB   8
#define NROWS (BJ * LSEQ)   // 98304

#define TS    128
#define PAD   132           // smem row stride (floats) for 128-wide tiles
#define HPAD  260           // smem row stride for 256-wide t tile

// -------- device scratch (static globals: allocation-free) --------
__device__ float g_inv[NROWS];            // 384 KB
__device__ float g_xagg[NROWS * DIM];     // 48 MB
__device__ float g_hln[NROWS * DOUT];     // 48 MB

// =================== Kernel 0: inverse L2 norms ===================
__global__ void knorm_kernel(const float* __restrict__ x) {
    int row  = blockIdx.x * 8 + (threadIdx.x >> 5);
    int lane = threadIdx.x & 31;
    const float* xr = x + (size_t)row * DIM;
    float s = 0.f;
    #pragma unroll
    for (int d = lane; d < DIM; d += 32) { float v = xr[d]; s = fmaf(v, v, s); }
    #pragma unroll
    for (int o = 16; o; o >>= 1) s += __shfl_xor_sync(0xffffffffu, s, o);
    if (lane == 0) {
        float n = sqrtf(s);
        g_inv[row] = 1.0f / fmaxf(n, 1e-12f);
    }
}

// ====== Kernel 1: sim GEMM + top-8 + gather-mean -> g_xagg ======
// grid (4, 192): blockIdx.x = 128-row tile within bj, blockIdx.y = bj
__global__ __launch_bounds__(256, 1) void ksim_kernel(const float* __restrict__ x) {
    extern __shared__ float sm[];
    float* sA    = sm;                 // [128][PAD] row tile (row-major l,d)
    float* sB    = sm + 16896;         // [128][PAD] col tile; reused as C
    float* sInvR = sm + 33792;         // [128]
    float* sInvC = sm + 33920;         // [128]
    float* sTV   = sm + 34048;         // [256][8]
    int*   sTI   = reinterpret_cast<int*>(sm + 36096);  // [256][8]
    int*   sIdx  = reinterpret_cast<int*>(sm + 38144);  // [128][8]

    const int bj  = blockIdx.y;
    const int rt  = blockIdx.x;
    const int tid = threadIdx.x;
    const int tx  = tid & 15;
    const int ty  = tid >> 4;
    const int r0  = rt * TS;

    const float* xb = x + (size_t)bj * LSEQ * DIM;

    // load A tile (rows r0..r0+127), coalesced float4, smem stride PAD
    #pragma unroll
    for (int it = 0; it < 16; ++it) {
        int e  = tid + it * 256;
        int l  = e >> 5;
        int d4 = (e & 31) * 4;
        float4 v = *reinterpret_cast<const float4*>(xb + (size_t)(r0 + l) * DIM + d4);
        *reinterpret_cast<float4*>(&sA[l * PAD + d4]) = v;
    }
    if (tid < TS) sInvR[tid] = g_inv[bj * LSEQ + r0 + tid];

    // per-thread running top-8 (thread owns one row-half of columns)
    float tv[KNB]; int ti[KNB];
    #pragma unroll
    for (int n = 0; n < KNB; ++n) { tv[n] = -1e30f; ti[n] = 0x7fffffff; }
    float vmin = -1e30f; int minpos = 0;
    const int half = tid >> 7;      // 0/1: scans cols [0,64) / [64,128) of each tile
    const int rrow = tid & 127;

    for (int ct = 0; ct < 4; ++ct) {
        const int c0 = ct * TS;
        __syncthreads();   // previous scan done before overwriting sB
        #pragma unroll
        for (int it = 0; it < 16; ++it) {
            int e  = tid + it * 256;
            int l  = e >> 5;
            int d4 = (e & 31) * 4;
            float4 v = *reinterpret_cast<const float4*>(xb + (size_t)(c0 + l) * DIM + d4);
            *reinterpret_cast<float4*>(&sB[l * PAD + d4]) = v;
        }
        if (tid < TS) sInvC[tid] = g_inv[bj * LSEQ + c0 + tid];
        __syncthreads();

        // 128x128 sim tile: thread (tx,ty) -> rows {ty+16i}, cols {tx+16j}
        float acc[8][8];
        #pragma unroll
        for (int i = 0; i < 8; ++i)
            #pragma unroll
            for (int j = 0; j < 8; ++j) acc[i][j] = 0.f;

        #pragma unroll 4
        for (int k = 0; k < DIM; ++k) {
            float a[8], bb[8];
            #pragma unroll
            for (int i = 0; i < 8; ++i) a[i]  = sA[(ty + 16 * i) * PAD + k];
            #pragma unroll
            for (int j = 0; j < 8; ++j) bb[j] = sB[(tx + 16 * j) * PAD + k];
            #pragma unroll
            for (int i = 0; i < 8; ++i)
                #pragma unroll
                for (int j = 0; j < 8; ++j) acc[i][j] = fmaf(a[i], bb[j], acc[i][j]);
        }
        __syncthreads();   // everyone done reading sB

        // write scaled sims back into sB as C[r][c]
        #pragma unroll
        for (int i = 0; i < 8; ++i) {
            int r = ty + 16 * i;
            float ir = sInvR[r];
            #pragma unroll
            for (int j = 0; j < 8; ++j) {
                int c = tx + 16 * j;
                sB[r * PAD + c] = acc[i][j] * ir * sInvC[c];
            }
        }
        __syncthreads();

        // scan this tile's half-row, maintain top-8
        const int cbase = half * 64;
        for (int cc = 0; cc < 64; ++cc) {
            float v = sB[rrow * PAD + cbase + cc];
            if (v > vmin) {
                tv[minpos] = v; ti[minpos] = c0 + cbase + cc;
                vmin = tv[0]; minpos = 0;
                #pragma unroll
                for (int n = 1; n < KNB; ++n)
                    if (tv[n] < vmin) { vmin = tv[n]; minpos = n; }
            }
        }
    }

    // publish candidates, merge halves (lower-index tie-break, matches lax.top_k)
    #pragma unroll
    for (int n = 0; n < KNB; ++n) { sTV[tid * 8 + n] = tv[n]; sTI[tid * 8 + n] = ti[n]; }
    __syncthreads();
    if (tid < TS) {
        float cv[16]; int ci[16];
        #pragma unroll
        for (int n = 0; n < 8; ++n) { cv[n] = sTV[tid * 8 + n];          ci[n] = sTI[tid * 8 + n]; }
        #pragma unroll
        for (int n = 0; n < 8; ++n) { cv[8 + n] = sTV[(tid + 128) * 8 + n]; ci[8 + n] = sTI[(tid + 128) * 8 + n]; }
        #pragma unroll
        for (int n = 0; n < KNB; ++n) {
            int best = 0; float bv = -1e31f; int bi = 0x7fffffff;
            #pragma unroll
            for (int m = 0; m < 16; ++m)
                if (cv[m] > bv || (cv[m] == bv && ci[m] < bi)) { bv = cv[m]; bi = ci[m]; best = m; }
            sIdx[tid * KNB + n] = bi;
            cv[best] = -1e31f; ci[best] = 0x7fffffff;
        }
    }
    __syncthreads();

    // gather-mean: x_agg[r][d] = mean of 8 neighbor rows of raw x
    float* outb = g_xagg + (size_t)(bj * LSEQ + r0) * DIM;
    for (int e = tid; e < TS * DIM; e += 256) {
        int r = e >> 7;
        int d = e & 127;
        float s = 0.f;
        #pragma unroll
        for (int n = 0; n < KNB; ++n) {
            int idx = sIdx[r * KNB + n];
            s += xb[(size_t)idx * DIM + d];
        }
        outb[(size_t)r * DIM + d] = s * 0.125f;
    }
}

// ====== Kernel 2: h = x_agg @ W + b ; LayerNorm -> g_hln ======
__global__ __launch_bounds__(256, 1) void kgemm_ln_kernel(
        const float* __restrict__ W, const float* __restrict__ bvec,
        const float* __restrict__ gamma, const float* __restrict__ beta) {
    extern __shared__ float sm[];
    float* sX = sm;            // [128][PAD] x_agg tile; reused for h
    float* sW = sm + 16896;    // [128][PAD] weights [k][c]

    const int tile = blockIdx.x;            // 0..767 (128-row tiles)
    const int tid = threadIdx.x, tx = tid & 15, ty = tid >> 4;
    const float* xa = g_xagg + (size_t)tile * TS * DIM;

    #pragma unroll
    for (int it = 0; it < 16; ++it) {
        int e  = tid + it * 256;
        int l  = e >> 5;
        int d4 = (e & 31) * 4;
        *reinterpret_cast<float4*>(&sX[l * PAD + d4]) =
            *reinterpret_cast<const float4*>(xa + (size_t)l * DIM + d4);
        *reinterpret_cast<float4*>(&sW[l * PAD + d4]) =
            *reinterpret_cast<const float4*>(W + (size_t)l * DOUT + d4);
    }
    __syncthreads();

    float acc[8][8];
    #pragma unroll
    for (int i = 0; i < 8; ++i)
        #pragma unroll
        for (int j = 0; j < 8; ++j) acc[i][j] = 0.f;

    #pragma unroll 4
    for (int k = 0; k < DIM; ++k) {
        float a[8], bb[8];
        #pragma unroll
        for (int i = 0; i < 8; ++i) a[i]  = sX[(ty + 16 * i) * PAD + k];
        #pragma unroll
        for (int j = 0; j < 8; ++j) bb[j] = sW[k * PAD + tx + 16 * j];
        #pragma unroll
        for (int i = 0; i < 8; ++i)
            #pragma unroll
            for (int j = 0; j < 8; ++j) acc[i][j] = fmaf(a[i], bb[j], acc[i][j]);
    }
    __syncthreads();

    // h (+bias) back into sX
    float bv[8];
    #pragma unroll
    for (int j = 0; j < 8; ++j) bv[j] = bvec[tx + 16 * j];
    #pragma unroll
    for (int i = 0; i < 8; ++i)
        #pragma unroll
        for (int j = 0; j < 8; ++j)
            sX[(ty + 16 * i) * PAD + tx + 16 * j] = acc[i][j] + bv[j];
    __syncthreads();

    // LayerNorm: 2 threads per row, combine via shfl_xor(1)
    const int r = tid >> 1, hf = tid & 1;
    float s = 0.f, s2 = 0.f;
    #pragma unroll 4
    for (int c = 0; c < 64; ++c) {
        float v = sX[r * PAD + hf * 64 + c];
        s += v; s2 = fmaf(v, v, s2);
    }
    s  += __shfl_xor_sync(0xffffffffu, s, 1);
    s2 += __shfl_xor_sync(0xffffffffu, s2, 1);
    float mu  = s * (1.0f / 128.0f);
    float var = s2 * (1.0f / 128.0f) - mu * mu;
    float rs  = rsqrtf(var + 1e-5f);
    float* o = g_hln + (size_t)tile * TS * DOUT + (size_t)r * DOUT;
    #pragma unroll 4
    for (int c = 0; c < 64; ++c) {
        int cc = hf * 64 + c;
        float v = sX[r * PAD + cc];
        o[cc] = (v - mu) * rs * gamma[cc] + beta[cc];
    }
}

// ====== Kernel 3: out = relu(hln @ W1 + b1) @ W2 + b2 ======
__global__ __launch_bounds__(256, 1) void kmlp_kernel(
        const float* __restrict__ W1, const float* __restrict__ b1,
        const float* __restrict__ W2, const float* __restrict__ b2,
        float* __restrict__ out) {
    extern __shared__ float sm[];
    float* sH  = sm;                   // [128][PAD]
    float* sT  = sm + 16896;           // [128][HPAD]
    float* sWc = sm + 16896 + 33280;   // [8][PAD] weight chunk

    const int tile = blockIdx.x;
    const int tid = threadIdx.x, tx = tid & 15, ty = tid >> 4;
    const float* h = g_hln + (size_t)tile * TS * DOUT;

    #pragma unroll
    for (int it = 0; it < 16; ++it) {
        int e  = tid + it * 256;
        int l  = e >> 5;
        int d4 = (e & 31) * 4;
        *reinterpret_cast<float4*>(&sH[l * PAD + d4]) =
            *reinterpret_cast<const float4*>(h + (size_t)l * DOUT + d4);
    }
    __syncthreads();

    // ---- stage 1: t = relu(h @ W1 + b1), 2 N-blocks of 128 cols ----
    for (int nb = 0; nb < 2; ++nb) {
        float acc[8][8];
        #pragma unroll
        for (int i = 0; i < 8; ++i)
            #pragma unroll
            for (int j = 0; j < 8; ++j) acc[i][j] = 0.f;

        for (int k0 = 0; k0 < 128; k0 += 8) {
            {   // load 8x128 chunk of W1
                int k  = tid >> 5;
                int c4 = (tid & 31) * 4;
                *reinterpret_cast<float4*>(&sWc[k * PAD + c4]) =
                    *reinterpret_cast<const float4*>(W1 + (size_t)(k0 + k) * HID + nb * 128 + c4);
            }
            __syncthreads();
            #pragma unroll
            for (int kk = 0; kk < 8; ++kk) {
                float a[8], bb[8];
                #pragma unroll
                for (int i = 0; i < 8; ++i) a[i]  = sH[(ty + 16 * i) * PAD + k0 + kk];
                #pragma unroll
                for (int j = 0; j < 8; ++j) bb[j] = sWc[kk * PAD + tx + 16 * j];
                #pragma unroll
                for (int i = 0; i < 8; ++i)
                    #pragma unroll
                    for (int j = 0; j < 8; ++j) acc[i][j] = fmaf(a[i], bb[j], acc[i][j]);
            }
            __syncthreads();
        }
        float bv[8];
        #pragma unroll
        for (int j = 0; j < 8; ++j) bv[j] = b1[nb * 128 + tx + 16 * j];
        #pragma unroll
        for (int i = 0; i < 8; ++i)
            #pragma unroll
            for (int j = 0; j < 8; ++j)
                sT[(ty + 16 * i) * HPAD + nb * 128 + tx + 16 * j] =
                    fmaxf(acc[i][j] + bv[j], 0.f);
    }
    __syncthreads();

    // ---- stage 2: out = t @ W2 + b2 ----
    float acc2[8][8];
    #pragma unroll
    for (int i = 0; i < 8; ++i)
        #pragma unroll
        for (int j = 0; j < 8; ++j) acc2[i][j] = 0.f;

    for (int k0 = 0; k0 < 256; k0 += 8) {
        {   // load 8x128 chunk of W2
            int k  = tid >> 5;
            int c4 = (tid & 31) * 4;
            *reinterpret_cast<float4*>(&sWc[k * PAD + c4]) =
                *reinterpret_cast<const float4*>(W2 + (size_t)(k0 + k) * DOUT + c4);
        }
        __syncthreads();
        #pragma unroll
        for (int kk = 0; kk < 8; ++kk) {
            float a[8], bb[8];
            #pragma unroll
            for (int i = 0; i < 8; ++i) a[i]  = sT[(ty + 16 * i) * HPAD + k0 + kk];
            #pragma unroll
            for (int j = 0; j < 8; ++j) bb[j] = sWc[kk * PAD + tx + 16 * j];
            #pragma unroll
            for (int i = 0; i < 8; ++i)
                #pragma unroll
                for (int j = 0; j < 8; ++j) acc2[i][j] = fmaf(a[i], bb[j], acc2[i][j]);
        }
        __syncthreads();
    }

    float bv2[8];
    #pragma unroll
    for (int j = 0; j < 8; ++j) bv2[j] = b2[tx + 16 * j];
    #pragma unroll
    for (int i = 0; i < 8; ++i)
        #pragma unroll
        for (int j = 0; j < 8; ++j)
            out[(size_t)(tile * TS + ty + 16 * i) * DOUT + tx + 16 * j] =
                acc2[i][j] + bv2[j];
}

// ============================ launcher ============================
extern "C" void kernel_launch(void* const* d_in, const int* in_sizes, int n_in,
                              void* d_out, int out_size) {
    (void)in_sizes; (void)n_in; (void)out_size;
    const float* x     = (const float*)d_in[0];
    const float* W     = (const float*)d_in[1];
    const float* bvec  = (const float*)d_in[2];
    const float* W1    = (const float*)d_in[3];
    const float* b1    = (const float*)d_in[4];
    const float* W2    = (const float*)d_in[5];
    const float* b2    = (const float*)d_in[6];
    const float* gamma = (const float*)d_in[7];
    const float* beta  = (const float*)d_in[8];
    float* out = (float*)d_out;

    const size_t SMEM1 = 156672;  // ksim
    const size_t SMEM2 = 135168;  // kgemm_ln
    const size_t SMEM3 = 204928;  // kmlp

    cudaFuncSetAttribute(ksim_kernel,     cudaFuncAttributeMaxDynamicSharedMemorySize, (int)SMEM1);
    cudaFuncSetAttribute(kgemm_ln_kernel, cudaFuncAttributeMaxDynamicSharedMemorySize, (int)SMEM2);
    cudaFuncSetAttribute(kmlp_kernel,     cudaFuncAttributeMaxDynamicSharedMemorySize, (int)SMEM3);

    knorm_kernel<<<NROWS / 8, 256>>>(x);
    ksim_kernel<<<dim3(4, BJ), 256, SMEM1>>>(x);
    kgemm_ln_kernel<<<NROWS / TS, 256, SMEM2>>>(W, bvec, gamma, beta);
    kmlp_kernel<<<NROWS / TS, 256, SMEM3>>>(W1, b1, W2, b2, out);
}

// round 14
// speedup vs baseline: 1.0521x; 1.0521x over previous
#include <cuda_runtime.h>
#include <math.h>

#define BJ    192
#define LSEQ  512
#define DIM   128
#define DOUT  128
#define HID   256
#define KNB   8
#define NROWS (BJ * LSEQ)   // 98304

#define TS    128
#define PAD   132           // smem row stride (floats) for 128-wide tiles
#define HPAD  260           // smem row stride for 256-wide t tile

// -------- device scratch (static globals: allocation-free) --------
__device__ float g_inv[NROWS];            // 384 KB
__device__ float g_xagg[NROWS * DIM];     // 48 MB
__device__ float g_hln[NROWS * DOUT];     // 48 MB

// =================== Kernel 0: inverse L2 norms ===================
__global__ void knorm_kernel(const float* __restrict__ x) {
    int row  = blockIdx.x * 8 + (threadIdx.x >> 5);
    int lane = threadIdx.x & 31;
    const float* xr = x + (size_t)row * DIM;
    float s = 0.f;
    #pragma unroll
    for (int d = lane; d < DIM; d += 32) { float v = xr[d]; s = fmaf(v, v, s); }
    #pragma unroll
    for (int o = 16; o; o >>= 1) s += __shfl_xor_sync(0xffffffffu, s, o);
    if (lane == 0) {
        float n = sqrtf(s);
        g_inv[row] = 1.0f / fmaxf(n, 1e-12f);
    }
}

// ====== Kernel 1: sim GEMM + top-8 + gather-mean -> g_xagg ======
// grid (4, 192): blockIdx.x = 128-row tile within bj, blockIdx.y = bj
__global__ __launch_bounds__(256, 1) void ksim_kernel(const float* __restrict__ x) {
    extern __shared__ float sm[];
    float* sA    = sm;                 // [128][PAD] row tile (row-major l,d)
    float* sB    = sm + 16896;         // [128][PAD] col tile; reused as C
    float* sInvR = sm + 33792;         // [128]
    float* sInvC = sm + 33920;         // [128]
    float* sTV   = sm + 34048;         // [256][8]
    int*   sTI   = reinterpret_cast<int*>(sm + 36096);  // [256][8]
    int*   sIdx  = reinterpret_cast<int*>(sm + 38144);  // [128][8]

    const int bj  = blockIdx.y;
    const int rt  = blockIdx.x;
    const int tid = threadIdx.x;
    const int tx  = tid & 15;
    const int ty  = tid >> 4;
    const int r0  = rt * TS;

    const float* xb = x + (size_t)bj * LSEQ * DIM;

    // load A tile (rows r0..r0+127), coalesced float4, smem stride PAD
    #pragma unroll
    for (int it = 0; it < 16; ++it) {
        int e  = tid + it * 256;
        int l  = e >> 5;
        int d4 = (e & 31) * 4;
        float4 v = *reinterpret_cast<const float4*>(xb + (size_t)(r0 + l) * DIM + d4);
        *reinterpret_cast<float4*>(&sA[l * PAD + d4]) = v;
    }
    if (tid < TS) sInvR[tid] = g_inv[bj * LSEQ + r0 + tid];

    // per-thread running top-8 (thread owns one row-half of columns)
    float tv[KNB]; int ti[KNB];
    #pragma unroll
    for (int n = 0; n < KNB; ++n) { tv[n] = -1e30f; ti[n] = 0x7fffffff; }
    float vmin = -1e30f; int minpos = 0;
    const int half = tid >> 7;      // 0/1: scans cols [0,64) / [64,128) of each tile
    const int rrow = tid & 127;

    for (int ct = 0; ct < 4; ++ct) {
        const int c0 = ct * TS;
        __syncthreads();   // previous scan done before overwriting sB
        #pragma unroll
        for (int it = 0; it < 16; ++it) {
            int e  = tid + it * 256;
            int l  = e >> 5;
            int d4 = (e & 31) * 4;
            float4 v = *reinterpret_cast<const float4*>(xb + (size_t)(c0 + l) * DIM + d4);
            *reinterpret_cast<float4*>(&sB[l * PAD + d4]) = v;
        }
        if (tid < TS) sInvC[tid] = g_inv[bj * LSEQ + c0 + tid];
        __syncthreads();

        // 128x128 sim tile: thread (tx,ty) -> rows {ty+16i}, cols {tx+16j}
        float acc[8][8];
        #pragma unroll
        for (int i = 0; i < 8; ++i)
            #pragma unroll
            for (int j = 0; j < 8; ++j) acc[i][j] = 0.f;

        #pragma unroll 4
        for (int k = 0; k < DIM; ++k) {
            float a[8], bb[8];
            #pragma unroll
            for (int i = 0; i < 8; ++i) a[i]  = sA[(ty + 16 * i) * PAD + k];
            #pragma unroll
            for (int j = 0; j < 8; ++j) bb[j] = sB[(tx + 16 * j) * PAD + k];
            #pragma unroll
            for (int i = 0; i < 8; ++i)
                #pragma unroll
                for (int j = 0; j < 8; ++j) acc[i][j] = fmaf(a[i], bb[j], acc[i][j]);
        }
        __syncthreads();   // everyone done reading sB

        // write scaled sims back into sB as C[r][c]
        #pragma unroll
        for (int i = 0; i < 8; ++i) {
            int r = ty + 16 * i;
            float ir = sInvR[r];
            #pragma unroll
            for (int j = 0; j < 8; ++j) {
                int c = tx + 16 * j;
                sB[r * PAD + c] = acc[i][j] * ir * sInvC[c];
            }
        }
        __syncthreads();

        // scan this tile's half-row, maintain top-8
        const int cbase = half * 64;
        for (int cc = 0; cc < 64; ++cc) {
            float v = sB[rrow * PAD + cbase + cc];
            if (v > vmin) {
                tv[minpos] = v; ti[minpos] = c0 + cbase + cc;
                vmin = tv[0]; minpos = 0;
                #pragma unroll
                for (int n = 1; n < KNB; ++n)
                    if (tv[n] < vmin) { vmin = tv[n]; minpos = n; }
            }
        }
    }

    // publish candidates, merge halves (lower-index tie-break, matches lax.top_k)
    #pragma unroll
    for (int n = 0; n < KNB; ++n) { sTV[tid * 8 + n] = tv[n]; sTI[tid * 8 + n] = ti[n]; }
    __syncthreads();
    if (tid < TS) {
        float cv[16]; int ci[16];
        #pragma unroll
        for (int n = 0; n < 8; ++n) { cv[n] = sTV[tid * 8 + n];          ci[n] = sTI[tid * 8 + n]; }
        #pragma unroll
        for (int n = 0; n < 8; ++n) { cv[8 + n] = sTV[(tid + 128) * 8 + n]; ci[8 + n] = sTI[(tid + 128) * 8 + n]; }
        #pragma unroll
        for (int n = 0; n < KNB; ++n) {
            int best = 0; float bv = -1e31f; int bi = 0x7fffffff;
            #pragma unroll
            for (int m = 0; m < 16; ++m)
                if (cv[m] > bv || (cv[m] == bv && ci[m] < bi)) { bv = cv[m]; bi = ci[m]; best = m; }
            sIdx[tid * KNB + n] = bi;
            cv[best] = -1e31f; ci[best] = 0x7fffffff;
        }
    }
    __syncthreads();

    // gather-mean: x_agg[r][d] = mean of 8 neighbor rows of raw x
    float* outb = g_xagg + (size_t)(bj * LSEQ + r0) * DIM;
    for (int e = tid; e < TS * DIM; e += 256) {
        int r = e >> 7;
        int d = e & 127;
        float s = 0.f;
        #pragma unroll
        for (int n = 0; n < KNB; ++n) {
            int idx = sIdx[r * KNB + n];
            s += xb[(size_t)idx * DIM + d];
        }
        outb[(size_t)r * DIM + d] = s * 0.125f;
    }
}

// ====== Kernel 2: h = x_agg @ W + b ; LayerNorm -> g_hln ======
__global__ __launch_bounds__(256, 1) void kgemm_ln_kernel(
        const float* __restrict__ W, const float* __restrict__ bvec,
        const float* __restrict__ gamma, const float* __restrict__ beta) {
    extern __shared__ float sm[];
    float* sX = sm;            // [128][PAD] x_agg tile; reused for h
    float* sW = sm + 16896;    // [128][PAD] weights [k][c]

    const int tile = blockIdx.x;            // 0..767 (128-row tiles)
    const int tid = threadIdx.x, tx = tid & 15, ty = tid >> 4;
    const float* xa = g_xagg + (size_t)tile * TS * DIM;

    #pragma unroll
    for (int it = 0; it < 16; ++it) {
        int e  = tid + it * 256;
        int l  = e >> 5;
        int d4 = (e & 31) * 4;
        *reinterpret_cast<float4*>(&sX[l * PAD + d4]) =
            *reinterpret_cast<const float4*>(xa + (size_t)l * DIM + d4);
        *reinterpret_cast<float4*>(&sW[l * PAD + d4]) =
            *reinterpret_cast<const float4*>(W + (size_t)l * DOUT + d4);
    }
    __syncthreads();

    float acc[8][8];
    #pragma unroll
    for (int i = 0; i < 8; ++i)
        #pragma unroll
        for (int j = 0; j < 8; ++j) acc[i][j] = 0.f;

    #pragma unroll 4
    for (int k = 0; k < DIM; ++k) {
        float a[8], bb[8];
        #pragma unroll
        for (int i = 0; i < 8; ++i) a[i]  = sX[(ty + 16 * i) * PAD + k];
        #pragma unroll
        for (int j = 0; j < 8; ++j) bb[j] = sW[k * PAD + tx + 16 * j];
        #pragma unroll
        for (int i = 0; i < 8; ++i)
            #pragma unroll
            for (int j = 0; j < 8; ++j) acc[i][j] = fmaf(a[i], bb[j], acc[i][j]);
    }
    __syncthreads();

    // h (+bias) back into sX
    float bv[8];
    #pragma unroll
    for (int j = 0; j < 8; ++j) bv[j] = bvec[tx + 16 * j];
    #pragma unroll
    for (int i = 0; i < 8; ++i)
        #pragma unroll
        for (int j = 0; j < 8; ++j)
            sX[(ty + 16 * i) * PAD + tx + 16 * j] = acc[i][j] + bv[j];
    __syncthreads();

    // LayerNorm: 2 threads per row, combine via shfl_xor(1)
    const int r = tid >> 1, hf = tid & 1;
    float s = 0.f, s2 = 0.f;
    #pragma unroll 4
    for (int c = 0; c < 64; ++c) {
        float v = sX[r * PAD + hf * 64 + c];
        s += v; s2 = fmaf(v, v, s2);
    }
    s  += __shfl_xor_sync(0xffffffffu, s, 1);
    s2 += __shfl_xor_sync(0xffffffffu, s2, 1);
    float mu  = s * (1.0f / 128.0f);
    float var = s2 * (1.0f / 128.0f) - mu * mu;
    float rs  = rsqrtf(var + 1e-5f);
    float* o = g_hln + (size_t)tile * TS * DOUT + (size_t)r * DOUT;
    #pragma unroll 4
    for (int c = 0; c < 64; ++c) {
        int cc = hf * 64 + c;
        float v = sX[r * PAD + cc];
        o[cc] = (v - mu) * rs * gamma[cc] + beta[cc];
    }
}

// ====== Kernel 3: out = relu(hln @ W1 + b1) @ W2 + b2 ======
__global__ __launch_bounds__(256, 1) void kmlp_kernel(
        const float* __restrict__ W1, const float* __restrict__ b1,
        const float* __restrict__ W2, const float* __restrict__ b2,
        float* __restrict__ out) {
    extern __shared__ float sm[];
    float* sH  = sm;                   // [128][PAD]
    float* sT  = sm + 16896;           // [128][HPAD]
    float* sWc = sm + 16896 + 33280;   // [8][PAD] weight chunk

    const int tile = blockIdx.x;
    const int tid = threadIdx.x, tx = tid & 15, ty = tid >> 4;
    const float* h = g_hln + (size_t)tile * TS * DOUT;

    #pragma unroll
    for (int it = 0; it < 16; ++it) {
        int e  = tid + it * 256;
        int l  = e >> 5;
        int d4 = (e & 31) * 4;
        *reinterpret_cast<float4*>(&sH[l * PAD + d4]) =
            *reinterpret_cast<const float4*>(h + (size_t)l * DOUT + d4);
    }
    __syncthreads();

    // ---- stage 1: t = relu(h @ W1 + b1), 2 N-blocks of 128 cols ----
    for (int nb = 0; nb < 2; ++nb) {
        float acc[8][8];
        #pragma unroll
        for (int i = 0; i < 8; ++i)
            #pragma unroll
            for (int j = 0; j < 8; ++j) acc[i][j] = 0.f;

        for (int k0 = 0; k0 < 128; k0 += 8) {
            {   // load 8x128 chunk of W1
                int k  = tid >> 5;
                int c4 = (tid & 31) * 4;
                *reinterpret_cast<float4*>(&sWc[k * PAD + c4]) =
                    *reinterpret_cast<const float4*>(W1 + (size_t)(k0 + k) * HID + nb * 128 + c4);
            }
            __syncthreads();
            #pragma unroll
            for (int kk = 0; kk < 8; ++kk) {
                float a[8], bb[8];
                #pragma unroll
                for (int i = 0; i < 8; ++i) a[i]  = sH[(ty + 16 * i) * PAD + k0 + kk];
                #pragma unroll
                for (int j = 0; j < 8; ++j) bb[j] = sWc[kk * PAD + tx + 16 * j];
                #pragma unroll
                for (int i = 0; i < 8; ++i)
                    #pragma unroll
                    for (int j = 0; j < 8; ++j) acc[i][j] = fmaf(a[i], bb[j], acc[i][j]);
            }
            __syncthreads();
        }
        float bv[8];
        #pragma unroll
        for (int j = 0; j < 8; ++j) bv[j] = b1[nb * 128 + tx + 16 * j];
        #pragma unroll
        for (int i = 0; i < 8; ++i)
            #pragma unroll
            for (int j = 0; j < 8; ++j)
                sT[(ty + 16 * i) * HPAD + nb * 128 + tx + 16 * j] =
                    fmaxf(acc[i][j] + bv[j], 0.f);
    }
    __syncthreads();

    // ---- stage 2: out = t @ W2 + b2 ----
    float acc2[8][8];
    #pragma unroll
    for (int i = 0; i < 8; ++i)
        #pragma unroll
        for (int j = 0; j < 8; ++j) acc2[i][j] = 0.f;

    for (int k0 = 0; k0 < 256; k0 += 8) {
        {   // load 8x128 chunk of W2
            int k  = tid >> 5;
            int c4 = (tid & 31) * 4;
            *reinterpret_cast<float4*>(&sWc[k * PAD + c4]) =
                *reinterpret_cast<const float4*>(W2 + (size_t)(k0 + k) * DOUT + c4);
        }
        __syncthreads();
        #pragma unroll
        for (int kk = 0; kk < 8; ++kk) {
            float a[8], bb[8];
            #pragma unroll
            for (int i = 0; i < 8; ++i) a[i]  = sT[(ty + 16 * i) * HPAD + k0 + kk];
            #pragma unroll
            for (int j = 0; j < 8; ++j) bb[j] = sWc[kk * PAD + tx + 16 * j];
            #pragma unroll
            for (int i = 0; i < 8; ++i)
                #pragma unroll
                for (int j = 0; j < 8; ++j) acc2[i][j] = fmaf(a[i], bb[j], acc2[i][j]);
        }
        __syncthreads();
    }

    float bv2[8];
    #pragma unroll
    for (int j = 0; j < 8; ++j) bv2[j] = b2[tx + 16 * j];
    #pragma unroll
    for (int i = 0; i < 8; ++i)
        #pragma unroll
        for (int j = 0; j < 8; ++j)
            out[(size_t)(tile * TS + ty + 16 * i) * DOUT + tx + 16 * j] =
                acc2[i][j] + bv2[j];
}

// ============================ launcher ============================
extern "C" void kernel_launch(void* const* d_in, const int* in_sizes, int n_in,
                              void* d_out, int out_size) {
    (void)in_sizes; (void)n_in; (void)out_size;
    const float* x     = (const float*)d_in[0];
    const float* W     = (const float*)d_in[1];
    const float* bvec  = (const float*)d_in[2];
    const float* W1    = (const float*)d_in[3];
    const float* b1    = (const float*)d_in[4];
    const float* W2    = (const float*)d_in[5];
    const float* b2    = (const float*)d_in[6];
    const float* gamma = (const float*)d_in[7];
    const float* beta  = (const float*)d_in[8];
    float* out = (float*)d_out;

    const size_t SMEM1 = 156672;  // ksim
    const size_t SMEM2 = 135168;  // kgemm_ln
    const size_t SMEM3 = 204928;  // kmlp

    cudaFuncSetAttribute(ksim_kernel,     cudaFuncAttributeMaxDynamicSharedMemorySize, (int)SMEM1);
    cudaFuncSetAttribute(kgemm_ln_kernel, cudaFuncAttributeMaxDynamicSharedMemorySize, (int)SMEM2);
    cudaFuncSetAttribute(kmlp_kernel,     cudaFuncAttributeMaxDynamicSharedMemorySize, (int)SMEM3);

    knorm_kernel<<<NROWS / 8, 256>>>(x);
    ksim_kernel<<<dim3(4, BJ), 256, SMEM1>>>(x);
    kgemm_ln_kernel<<<NROWS / TS, 256, SMEM2>>>(W, bvec, gamma, beta);
    kmlp_kernel<<<NROWS / TS, 256, SMEM3>>>(W1, b1, W2, b2, out);
}

// round 15
// speedup vs baseline: 1.0523x; 1.0002x over previous
#include <cuda_runtime.h>
#include <math.h>

#define BJ    192
#define LSEQ  512
#define DIM   128
#define DOUT  128
#define HID   256
#define KNB   8
#define NROWS (BJ * LSEQ)   // 98304

#define TS    128
#define PAD   132           // smem row stride (floats) for 128-wide tiles
#define HPAD  260           // smem row stride for 256-wide t tile

// -------- device scratch (static globals: allocation-free) --------
__device__ float g_inv[NROWS];            // 384 KB
__device__ float g_xagg[NROWS * DIM];     // 48 MB
__device__ float g_hln[NROWS * DOUT];     // 48 MB

// =================== Kernel 0: inverse L2 norms ===================
__global__ void knorm_kernel(const float* __restrict__ x) {
    int row  = blockIdx.x * 8 + (threadIdx.x >> 5);
    int lane = threadIdx.x & 31;
    const float* xr = x + (size_t)row * DIM;
    float s = 0.f;
    #pragma unroll
    for (int d = lane; d < DIM; d += 32) { float v = xr[d]; s = fmaf(v, v, s); }
    #pragma unroll
    for (int o = 16; o; o >>= 1) s += __shfl_xor_sync(0xffffffffu, s, o);
    if (lane == 0) {
        float n = sqrtf(s);
        g_inv[row] = 1.0f / fmaxf(n, 1e-12f);
    }
}

// ====== Kernel 1: sim GEMM + top-8 + gather-mean -> g_xagg ======
// grid (4, 192): blockIdx.x = 128-row tile within bj, blockIdx.y = bj
__global__ __launch_bounds__(256, 1) void ksim_kernel(const float* __restrict__ x) {
    extern __shared__ float sm[];
    float* sA    = sm;                 // [128][PAD] row tile (row-major l,d)
    float* sB    = sm + 16896;         // [128][PAD] col tile; reused as C
    float* sInvR = sm + 33792;         // [128]
    float* sInvC = sm + 33920;         // [128]
    float* sTV   = sm + 34048;         // [256][8]
    int*   sTI   = reinterpret_cast<int*>(sm + 36096);  // [256][8]
    int*   sIdx  = reinterpret_cast<int*>(sm + 38144);  // [128][8]

    const int bj  = blockIdx.y;
    const int rt  = blockIdx.x;
    const int tid = threadIdx.x;
    const int tx  = tid & 15;
    const int ty  = tid >> 4;
    const int r0  = rt * TS;

    const float* xb = x + (size_t)bj * LSEQ * DIM;

    // load A tile (rows r0..r0+127), coalesced float4, smem stride PAD
    #pragma unroll
    for (int it = 0; it < 16; ++it) {
        int e  = tid + it * 256;
        int l  = e >> 5;
        int d4 = (e & 31) * 4;
        float4 v = *reinterpret_cast<const float4*>(xb + (size_t)(r0 + l) * DIM + d4);
        *reinterpret_cast<float4*>(&sA[l * PAD + d4]) = v;
    }
    if (tid < TS) sInvR[tid] = g_inv[bj * LSEQ + r0 + tid];

    // per-thread running top-8 (thread owns one row-half of columns)
    float tv[KNB]; int ti[KNB];
    #pragma unroll
    for (int n = 0; n < KNB; ++n) { tv[n] = -1e30f; ti[n] = 0x7fffffff; }
    float vmin = -1e30f; int minpos = 0;
    const int half = tid >> 7;      // 0/1: scans cols [0,64) / [64,128) of each tile
    const int rrow = tid & 127;

    for (int ct = 0; ct < 4; ++ct) {
        const int c0 = ct * TS;
        __syncthreads();   // previous scan done before overwriting sB
        #pragma unroll
        for (int it = 0; it < 16; ++it) {
            int e  = tid + it * 256;
            int l  = e >> 5;
            int d4 = (e & 31) * 4;
            float4 v = *reinterpret_cast<const float4*>(xb + (size_t)(c0 + l) * DIM + d4);
            *reinterpret_cast<float4*>(&sB[l * PAD + d4]) = v;
        }
        if (tid < TS) sInvC[tid] = g_inv[bj * LSEQ + c0 + tid];
        __syncthreads();

        // 128x128 sim tile: thread (tx,ty) -> rows {ty+16i}, cols {tx+16j}
        float acc[8][8];
        #pragma unroll
        for (int i = 0; i < 8; ++i)
            #pragma unroll
            for (int j = 0; j < 8; ++j) acc[i][j] = 0.f;

        #pragma unroll 4
        for (int k = 0; k < DIM; ++k) {
            float a[8], bb[8];
            #pragma unroll
            for (int i = 0; i < 8; ++i) a[i]  = sA[(ty + 16 * i) * PAD + k];
            #pragma unroll
            for (int j = 0; j < 8; ++j) bb[j] = sB[(tx + 16 * j) * PAD + k];
            #pragma unroll
            for (int i = 0; i < 8; ++i)
                #pragma unroll
                for (int j = 0; j < 8; ++j) acc[i][j] = fmaf(a[i], bb[j], acc[i][j]);
        }
        __syncthreads();   // everyone done reading sB

        // write scaled sims back into sB as C[r][c]
        #pragma unroll
        for (int i = 0; i < 8; ++i) {
            int r = ty + 16 * i;
            float ir = sInvR[r];
            #pragma unroll
            for (int j = 0; j < 8; ++j) {
                int c = tx + 16 * j;
                sB[r * PAD + c] = acc[i][j] * ir * sInvC[c];
            }
        }
        __syncthreads();

        // scan this tile's half-row, maintain top-8
        const int cbase = half * 64;
        for (int cc = 0; cc < 64; ++cc) {
            float v = sB[rrow * PAD + cbase + cc];
            if (v > vmin) {
                tv[minpos] = v; ti[minpos] = c0 + cbase + cc;
                vmin = tv[0]; minpos = 0;
                #pragma unroll
                for (int n = 1; n < KNB; ++n)
                    if (tv[n] < vmin) { vmin = tv[n]; minpos = n; }
            }
        }
    }

    // publish candidates, merge halves (lower-index tie-break, matches lax.top_k)
    #pragma unroll
    for (int n = 0; n < KNB; ++n) { sTV[tid * 8 + n] = tv[n]; sTI[tid * 8 + n] = ti[n]; }
    __syncthreads();
    if (tid < TS) {
        float cv[16]; int ci[16];
        #pragma unroll
        for (int n = 0; n < 8; ++n) { cv[n] = sTV[tid * 8 + n];          ci[n] = sTI[tid * 8 + n]; }
        #pragma unroll
        for (int n = 0; n < 8; ++n) { cv[8 + n] = sTV[(tid + 128) * 8 + n]; ci[8 + n] = sTI[(tid + 128) * 8 + n]; }
        #pragma unroll
        for (int n = 0; n < KNB; ++n) {
            int best = 0; float bv = -1e31f; int bi = 0x7fffffff;
            #pragma unroll
            for (int m = 0; m < 16; ++m)
                if (cv[m] > bv || (cv[m] == bv && ci[m] < bi)) { bv = cv[m]; bi = ci[m]; best = m; }
            sIdx[tid * KNB + n] = bi;
            cv[best] = -1e31f; ci[best] = 0x7fffffff;
        }
    }
    __syncthreads();

    // gather-mean: x_agg[r][d] = mean of 8 neighbor rows of raw x
    float* outb = g_xagg + (size_t)(bj * LSEQ + r0) * DIM;
    for (int e = tid; e < TS * DIM; e += 256) {
        int r = e >> 7;
        int d = e & 127;
        float s = 0.f;
        #pragma unroll
        for (int n = 0; n < KNB; ++n) {
            int idx = sIdx[r * KNB + n];
            s += xb[(size_t)idx * DIM + d];
        }
        outb[(size_t)r * DIM + d] = s * 0.125f;
    }
}

// ====== Kernel 2: h = x_agg @ W + b ; LayerNorm -> g_hln ======
__global__ __launch_bounds__(256, 1) void kgemm_ln_kernel(
        const float* __restrict__ W, const float* __restrict__ bvec,
        const float* __restrict__ gamma, const float* __restrict__ beta) {
    extern __shared__ float sm[];
    float* sX = sm;            // [128][PAD] x_agg tile; reused for h
    float* sW = sm + 16896;    // [128][PAD] weights [k][c]

    const int tile = blockIdx.x;            // 0..767 (128-row tiles)
    const int tid = threadIdx.x, tx = tid & 15, ty = tid >> 4;
    const float* xa = g_xagg + (size_t)tile * TS * DIM;

    #pragma unroll
    for (int it = 0; it < 16; ++it) {
        int e  = tid + it * 256;
        int l  = e >> 5;
        int d4 = (e & 31) * 4;
        *reinterpret_cast<float4*>(&sX[l * PAD + d4]) =
            *reinterpret_cast<const float4*>(xa + (size_t)l * DIM + d4);
        *reinterpret_cast<float4*>(&sW[l * PAD + d4]) =
            *reinterpret_cast<const float4*>(W + (size_t)l * DOUT + d4);
    }
    __syncthreads();

    float acc[8][8];
    #pragma unroll
    for (int i = 0; i < 8; ++i)
        #pragma unroll
        for (int j = 0; j < 8; ++j) acc[i][j] = 0.f;

    #pragma unroll 4
    for (int k = 0; k < DIM; ++k) {
        float a[8], bb[8];
        #pragma unroll
        for (int i = 0; i < 8; ++i) a[i]  = sX[(ty + 16 * i) * PAD + k];
        #pragma unroll
        for (int j = 0; j < 8; ++j) bb[j] = sW[k * PAD + tx + 16 * j];
        #pragma unroll
        for (int i = 0; i < 8; ++i)
            #pragma unroll
            for (int j = 0; j < 8; ++j) acc[i][j] = fmaf(a[i], bb[j], acc[i][j]);
    }
    __syncthreads();

    // h (+bias) back into sX
    float bv[8];
    #pragma unroll
    for (int j = 0; j < 8; ++j) bv[j] = bvec[tx + 16 * j];
    #pragma unroll
    for (int i = 0; i < 8; ++i)
        #pragma unroll
        for (int j = 0; j < 8; ++j)
            sX[(ty + 16 * i) * PAD + tx + 16 * j] = acc[i][j] + bv[j];
    __syncthreads();

    // LayerNorm: 2 threads per row, combine via shfl_xor(1)
    const int r = tid >> 1, hf = tid & 1;
    float s = 0.f, s2 = 0.f;
    #pragma unroll 4
    for (int c = 0; c < 64; ++c) {
        float v = sX[r * PAD + hf * 64 + c];
        s += v; s2 = fmaf(v, v, s2);
    }
    s  += __shfl_xor_sync(0xffffffffu, s, 1);
    s2 += __shfl_xor_sync(0xffffffffu, s2, 1);
    float mu  = s * (1.0f / 128.0f);
    float var = s2 * (1.0f / 128.0f) - mu * mu;
    float rs  = rsqrtf(var + 1e-5f);
    float* o = g_hln + (size_t)tile * TS * DOUT + (size_t)r * DOUT;
    #pragma unroll 4
    for (int c = 0; c < 64; ++c) {
        int cc = hf * 64 + c;
        float v = sX[r * PAD + cc];
        o[cc] = (v - mu) * rs * gamma[cc] + beta[cc];
    }
}

// ====== Kernel 3: out = relu(hln @ W1 + b1) @ W2 + b2 ======
__global__ __launch_bounds__(256, 1) void kmlp_kernel(
        const float* __restrict__ W1, const float* __restrict__ b1,
        const float* __restrict__ W2, const float* __restrict__ b2,
        float* __restrict__ out) {
    extern __shared__ float sm[];
    float* sH  = sm;                   // [128][PAD]
    float* sT  = sm + 16896;           // [128][HPAD]
    float* sWc = sm + 16896 + 33280;   // [8][PAD] weight chunk

    const int tile = blockIdx.x;
    const int tid = threadIdx.x, tx = tid & 15, ty = tid >> 4;
    const float* h = g_hln + (size_t)tile * TS * DOUT;

    #pragma unroll
    for (int it = 0; it < 16; ++it) {
        int e  = tid + it * 256;
        int l  = e >> 5;
        int d4 = (e & 31) * 4;
        *reinterpret_cast<float4*>(&sH[l * PAD + d4]) =
            *reinterpret_cast<const float4*>(h + (size_t)l * DOUT + d4);
    }
    __syncthreads();

    // ---- stage 1: t = relu(h @ W1 + b1), 2 N-blocks of 128 cols ----
    for (int nb = 0; nb < 2; ++nb) {
        float acc[8][8];
        #pragma unroll
        for (int i = 0; i < 8; ++i)
            #pragma unroll
            for (int j = 0; j < 8; ++j) acc[i][j] = 0.f;

        for (int k0 = 0; k0 < 128; k0 += 8) {
            {   // load 8x128 chunk of W1
                int k  = tid >> 5;
                int c4 = (tid & 31) * 4;
                *reinterpret_cast<float4*>(&sWc[k * PAD + c4]) =
                    *reinterpret_cast<const float4*>(W1 + (size_t)(k0 + k) * HID + nb * 128 + c4);
            }
            __syncthreads();
            #pragma unroll
            for (int kk = 0; kk < 8; ++kk) {
                float a[8], bb[8];
                #pragma unroll
                for (int i = 0; i < 8; ++i) a[i]  = sH[(ty + 16 * i) * PAD + k0 + kk];
                #pragma unroll
                for (int j = 0; j < 8; ++j) bb[j] = sWc[kk * PAD + tx + 16 * j];
                #pragma unroll
                for (int i = 0; i < 8; ++i)
                    #pragma unroll
                    for (int j = 0; j < 8; ++j) acc[i][j] = fmaf(a[i], bb[j], acc[i][j]);
            }
            __syncthreads();
        }
        float bv[8];
        #pragma unroll
        for (int j = 0; j < 8; ++j) bv[j] = b1[nb * 128 + tx + 16 * j];
        #pragma unroll
        for (int i = 0; i < 8; ++i)
            #pragma unroll
            for (int j = 0; j < 8; ++j)
                sT[(ty + 16 * i) * HPAD + nb * 128 + tx + 16 * j] =
                    fmaxf(acc[i][j] + bv[j], 0.f);
    }
    __syncthreads();

    // ---- stage 2: out = t @ W2 + b2 ----
    float acc2[8][8];
    #pragma unroll
    for (int i = 0; i < 8; ++i)
        #pragma unroll
        for (int j = 0; j < 8; ++j) acc2[i][j] = 0.f;

    for (int k0 = 0; k0 < 256; k0 += 8) {
        {   // load 8x128 chunk of W2
            int k  = tid >> 5;
            int c4 = (tid & 31) * 4;
            *reinterpret_cast<float4*>(&sWc[k * PAD + c4]) =
                *reinterpret_cast<const float4*>(W2 + (size_t)(k0 + k) * DOUT + c4);
        }
        __syncthreads();
        #pragma unroll
        for (int kk = 0; kk < 8; ++kk) {
            float a[8], bb[8];
            #pragma unroll
            for (int i = 0; i < 8; ++i) a[i]  = sT[(ty + 16 * i) * HPAD + k0 + kk];
            #pragma unroll
            for (int j = 0; j < 8; ++j) bb[j] = sWc[kk * PAD + tx + 16 * j];
            #pragma unroll
            for (int i = 0; i < 8; ++i)
                #pragma unroll
                for (int j = 0; j < 8; ++j) acc2[i][j] = fmaf(a[i], bb[j], acc2[i][j]);
        }
        __syncthreads();
    }

    float bv2[8];
    #pragma unroll
    for (int j = 0; j < 8; ++j) bv2[j] = b2[tx + 16 * j];
    #pragma unroll
    for (int i = 0; i < 8; ++i)
        #pragma unroll
        for (int j = 0; j < 8; ++j)
            out[(size_t)(tile * TS + ty + 16 * i) * DOUT + tx + 16 * j] =
                acc2[i][j] + bv2[j];
}

// ============================ launcher ============================
extern "C" void kernel_launch(void* const* d_in, const int* in_sizes, int n_in,
                              void* d_out, int out_size) {
    (void)in_sizes; (void)n_in; (void)out_size;
    const float* x     = (const float*)d_in[0];
    const float* W     = (const float*)d_in[1];
    const float* bvec  = (const float*)d_in[2];
    const float* W1    = (const float*)d_in[3];
    const float* b1    = (const float*)d_in[4];
    const float* W2    = (const float*)d_in[5];
    const float* b2    = (const float*)d_in[6];
    const float* gamma = (const float*)d_in[7];
    const float* beta  = (const float*)d_in[8];
    float* out = (float*)d_out;

    const size_t SMEM1 = 156672;  // ksim
    const size_t SMEM2 = 135168;  // kgemm_ln
    const size_t SMEM3 = 204928;  // kmlp

    cudaFuncSetAttribute(ksim_kernel,     cudaFuncAttributeMaxDynamicSharedMemorySize, (int)SMEM1);
    cudaFuncSetAttribute(kgemm_ln_kernel, cudaFuncAttributeMaxDynamicSharedMemorySize, (int)SMEM2);
    cudaFuncSetAttribute(kmlp_kernel,     cudaFuncAttributeMaxDynamicSharedMemorySize, (int)SMEM3);

    knorm_kernel<<<NROWS / 8, 256>>>(x);
    ksim_kernel<<<dim3(4, BJ), 256, SMEM1>>>(x);
    kgemm_ln_kernel<<<NROWS / TS, 256, SMEM2>>>(W, bvec, gamma, beta);
    kmlp_kernel<<<NROWS / TS, 256, SMEM3>>>(W1, b1, W2, b2, out);
}